// round 2
// baseline (speedup 1.0000x reference)
#include <cuda_runtime.h>

// dct: [16, 64, 256, 256] fp32, mean/std: [64] fp32, out: [16, 1, 2048, 2048] fp32
#define HW      65536        // 256*256
#define OUTW    2048

__global__ __launch_bounds__(256, 2) void idct_kernel(
    const float* __restrict__ dct,
    const float* __restrict__ mean_,
    const float* __restrict__ std_,
    float* __restrict__ out)
{
    // s_hx[u][xp] = 0.5*c_u*cos((2*xp+1)u*pi/16)            (xp = 0..3, butterfly)
    // s_hy[v][yp] = 0.5*c_v*cos((2*yp+1)v*pi/16) / 255      (yp = 0..3)
    __shared__ float s_hx[8][4];
    __shared__ float s_hy[8][4];
    __shared__ float s_std[64];
    __shared__ float s_mean[64];

    int tid = threadIdx.x;
    if (tid < 64) {
        int u = tid >> 3, x = tid & 7;
        float c = (u == 0) ? 0.70710678118654752440f : 1.0f;
        float h = cospif((float)((2 * x + 1) * u) * (1.0f / 16.0f));
        float v = 0.5f * c * h;
        if (x < 4) {
            s_hx[u][x] = v;
            s_hy[u][x] = v * (1.0f / 255.0f);
        }
        s_std[tid]  = std_[tid];
        s_mean[tid] = mean_[tid];
    }
    __syncthreads();

    unsigned gid = blockIdx.x * 256u + (unsigned)tid;    // 0 .. 16*65536-1
    unsigned b   = gid >> 16;
    unsigned pos = gid & 65535u;                          // h*256 + w
    const float* src = dct + (size_t)b * 64u * HW + pos;

    // ---- Front-batched loads: 64 independent LDGs in flight per thread ----
    float d[64];
    #pragma unroll
    for (int c = 0; c < 64; c++)
        d[c] = __ldcs(src + (size_t)c * HW);

    // ---- Destandardize + y-pass (v -> y), even/odd butterfly ----
    // g[u][y] = sum_v s_hy[v][y] * (d[u*8+v]*std+mean);  d dies as g is born.
    float g[8][8];
    #pragma unroll
    for (int u = 0; u < 8; u++) {
        float t[8];
        #pragma unroll
        for (int v = 0; v < 8; v++) {
            int c = u * 8 + v;
            t[v] = fmaf(d[c], s_std[c], s_mean[c]);
        }
        #pragma unroll
        for (int yp = 0; yp < 4; yp++) {
            float te = 0.0f, to = 0.0f;
            #pragma unroll
            for (int vp = 0; vp < 4; vp++) {
                te = fmaf(s_hy[2 * vp    ][yp], t[2 * vp    ], te);
                to = fmaf(s_hy[2 * vp + 1][yp], t[2 * vp + 1], to);
            }
            g[u][yp]     = te + to;
            g[u][7 - yp] = te - to;
        }
    }

    // ---- x-pass (u -> x) per output row pair, write immediately ----
    unsigned hh = pos >> 8, ww = pos & 255u;
    float* dst = out + (size_t)b * ((size_t)OUTW * OUTW)
                     + (size_t)hh * 8 * OUTW + (size_t)ww * 8;

    const float K = 128.0f / 255.0f;   // +128 then /255, folded into even acc
    #pragma unroll
    for (int xp = 0; xp < 4; xp++) {
        float rE[8], rO[8];
        #pragma unroll
        for (int y = 0; y < 8; y++) { rE[y] = K; rO[y] = 0.0f; }

        #pragma unroll
        for (int up = 0; up < 4; up++) {
            float we = s_hx[2 * up    ][xp];
            float wo = s_hx[2 * up + 1][xp];
            #pragma unroll
            for (int y = 0; y < 8; y++) {
                rE[y] = fmaf(we, g[2 * up    ][y], rE[y]);
                rO[y] = fmaf(wo, g[2 * up + 1][y], rO[y]);
            }
        }

        float4 a, bq, c4, d4;
        a.x  = rE[0] + rO[0];  a.y  = rE[1] + rO[1];
        a.z  = rE[2] + rO[2];  a.w  = rE[3] + rO[3];
        bq.x = rE[4] + rO[4];  bq.y = rE[5] + rO[5];
        bq.z = rE[6] + rO[6];  bq.w = rE[7] + rO[7];
        c4.x = rE[0] - rO[0];  c4.y = rE[1] - rO[1];
        c4.z = rE[2] - rO[2];  c4.w = rE[3] - rO[3];
        d4.x = rE[4] - rO[4];  d4.y = rE[5] - rO[5];
        d4.z = rE[6] - rO[6];  d4.w = rE[7] - rO[7];

        __stcs((float4*)(dst + (size_t)xp * OUTW),           a);
        __stcs((float4*)(dst + (size_t)xp * OUTW + 4),       bq);
        __stcs((float4*)(dst + (size_t)(7 - xp) * OUTW),     c4);
        __stcs((float4*)(dst + (size_t)(7 - xp) * OUTW + 4), d4);
    }
}

extern "C" void kernel_launch(void* const* d_in, const int* in_sizes, int n_in,
                              void* d_out, int out_size)
{
    (void)in_sizes; (void)n_in; (void)out_size;
    const float* dct   = (const float*)d_in[0];
    const float* mean_ = (const float*)d_in[1];
    const float* std_  = (const float*)d_in[2];
    float* out = (float*)d_out;
    // 16*256*256 = 1,048,576 blocks of 8x8 pixels, 1 thread each.
    idct_kernel<<<4096, 256>>>(dct, mean_, std_, out);
}